// round 2
// baseline (speedup 1.0000x reference)
#include <cuda_runtime.h>

#define N_NODES 100000
#define N_EDGES 3200000
#define F_IN    512
#define HID     256
#define N_CLS   32
#define KSTEPS  10

// ---------------- device scratch (no runtime allocation allowed) ----------------
__device__ __align__(128) float g_z[(size_t)N_NODES * HID];      // relu(x@W1+b1)
__device__ __align__(128) float g_h0[(size_t)N_NODES * N_CLS];   // ping
__device__ __align__(128) float g_h1[(size_t)N_NODES * N_CLS];   // pong
__device__ __align__(128) float g_acc[(size_t)N_NODES * N_CLS];  // gamma-weighted sum
__device__ __align__(128) float g_dinv[N_NODES];                 // deg^-1/2
__device__ __align__(128) float g_norm[N_EDGES];                 // dinv[src]*dinv[dst]
__device__ __align__(128) int   g_src[N_EDGES];
__device__ __align__(128) int   g_dst[N_EDGES];
__device__ int g_is64;

// ---------------- edge index dtype sniff + convert ----------------
// int64 layout: odd 32-bit words are the zero high-halves of values < 2^31.
// int32 layout: odd words are random node ids; 16 all-zero is impossible in practice.
__global__ void k_sniff(const unsigned* __restrict__ raw) {
    unsigned orv = 0;
#pragma unroll
    for (int i = 0; i < 16; i++) orv |= raw[2 * i + 1];
    g_is64 = (orv == 0u) ? 1 : 0;
}

__global__ void k_cvt(const void* __restrict__ raw) {
    int i = blockIdx.x * blockDim.x + threadIdx.x;
    if (i >= 2 * N_EDGES) return;
    int v;
    if (g_is64) v = (int)((const long long*)raw)[i];
    else        v = ((const int*)raw)[i];
    if (i < N_EDGES) g_src[i] = v;
    else             g_dst[i - N_EDGES] = v;
}

// ---------------- degree / norm ----------------
__global__ void k_deg_init() {
    int i = blockIdx.x * blockDim.x + threadIdx.x;
    if (i < N_NODES) g_dinv[i] = 1.0f;   // self-loop contributes 1
}

__global__ void k_deg_count() {
    int e = blockIdx.x * blockDim.x + threadIdx.x;
    if (e < N_EDGES) atomicAdd(&g_dinv[g_dst[e]], 1.0f);
}

__global__ void k_deg_fin() {
    int i = blockIdx.x * blockDim.x + threadIdx.x;
    if (i < N_NODES) g_dinv[i] = rsqrtf(g_dinv[i]);
}

__global__ void k_norm() {
    int e = blockIdx.x * blockDim.x + threadIdx.x;
    if (e < N_EDGES) g_norm[e] = g_dinv[g_src[e]] * g_dinv[g_dst[e]];
}

// ---------------- GEMM1: g_z = relu(x @ W1 + b1)   [M=100000, K=512, N=256] ----------------
__global__ __launch_bounds__(256) void k_gemm1(const float* __restrict__ A,
                                               const float* __restrict__ W,
                                               const float* __restrict__ bias) {
    __shared__ __align__(16) float As[8][128];
    __shared__ __align__(16) float Bs[8][128];

    const int tid = threadIdx.x;
    const int tr = tid >> 4;       // 0..15
    const int tc = tid & 15;       // 0..15
    const int rowBase = blockIdx.y * 128;
    const int colBase = blockIdx.x * 128;

    float acc[8][8];
#pragma unroll
    for (int i = 0; i < 8; i++)
#pragma unroll
        for (int j = 0; j < 8; j++) acc[i][j] = 0.0f;

    const int ar = tid >> 1;            // 0..127
    const int ac = (tid & 1) * 4;       // 0 or 4
    const int br = tid >> 5;            // 0..7
    const int bc = (tid & 31) * 4;      // 0..124

    for (int k0 = 0; k0 < F_IN; k0 += 8) {
        float4 av = make_float4(0.f, 0.f, 0.f, 0.f);
        int grow = rowBase + ar;
        if (grow < N_NODES)
            av = *(const float4*)(A + (size_t)grow * F_IN + k0 + ac);
        As[ac + 0][ar] = av.x;
        As[ac + 1][ar] = av.y;
        As[ac + 2][ar] = av.z;
        As[ac + 3][ar] = av.w;

        float4 bv = *(const float4*)(W + (size_t)(k0 + br) * HID + colBase + bc);
        *(float4*)(&Bs[br][bc]) = bv;

        __syncthreads();

#pragma unroll
        for (int kk = 0; kk < 8; kk++) {
            float ra[8], rb[8];
#pragma unroll
            for (int i = 0; i < 8; i++) ra[i] = As[kk][tr * 8 + i];
#pragma unroll
            for (int j = 0; j < 8; j++) rb[j] = Bs[kk][tc * 8 + j];
#pragma unroll
            for (int i = 0; i < 8; i++)
#pragma unroll
                for (int j = 0; j < 8; j++) acc[i][j] += ra[i] * rb[j];
        }
        __syncthreads();
    }

#pragma unroll
    for (int i = 0; i < 8; i++) {
        int row = rowBase + tr * 8 + i;
        if (row >= N_NODES) continue;
#pragma unroll
        for (int j = 0; j < 8; j += 4) {
            int col = colBase + tc * 8 + j;
            float4 o;
            o.x = fmaxf(acc[i][j + 0] + bias[col + 0], 0.f);
            o.y = fmaxf(acc[i][j + 1] + bias[col + 1], 0.f);
            o.z = fmaxf(acc[i][j + 2] + bias[col + 2], 0.f);
            o.w = fmaxf(acc[i][j + 3] + bias[col + 3], 0.f);
            *(float4*)(g_z + (size_t)row * HID + col) = o;
        }
    }
}

// ---------------- GEMM2: g_h0 = g_z @ W2 + b2 ; g_acc = gamma[0]*g_h0 ----------------
__global__ __launch_bounds__(256) void k_gemm2(const float* __restrict__ W2,
                                               const float* __restrict__ b2,
                                               const float* __restrict__ gamma) {
    __shared__ __align__(16) float w2s[HID * N_CLS];   // 32 KB
    __shared__ __align__(16) float zs[8 * HID];        // 8 KB

    const int tid = threadIdx.x;
    for (int i = tid; i < HID * N_CLS; i += 256) w2s[i] = W2[i];

    const int rowBase = blockIdx.x * 8;
    for (int i = tid; i < 8 * HID; i += 256) {
        int r = rowBase + (i >> 8);
        zs[i] = (r < N_NODES) ? g_z[(size_t)r * HID + (i & 255)] : 0.f;
    }
    __syncthreads();

    const int r = tid >> 5;      // warp = row
    const int c = tid & 31;      // lane = class
    float s = b2[c];
#pragma unroll 8
    for (int k = 0; k < HID; k++)
        s += zs[r * HID + k] * w2s[k * N_CLS + c];

    int row = rowBase + r;
    if (row < N_NODES) {
        size_t o = (size_t)row * N_CLS + c;
        g_h0[o] = s;
        g_acc[o] = gamma[0] * s;
    }
}

// ---------------- propagation: self-loop init (+ fused gamma-axpy of previous h_k) ----------------
__global__ void k_prep(int cur, int gidx, const float* __restrict__ gamma) {
    int idx = blockIdx.x * blockDim.x + threadIdx.x;   // one float4
    if (idx >= N_NODES * N_CLS / 4) return;
    const float* hc = cur ? g_h1 : g_h0;
    float* hn = cur ? g_h0 : g_h1;

    int n = idx >> 3;                 // node (8 float4s per node)
    float di = g_dinv[n];
    float w = di * di;                // self-loop norm = 1/deg
    float4 v = *(const float4*)(hc + (size_t)idx * 4);
    float4 o = make_float4(w * v.x, w * v.y, w * v.z, w * v.w);
    *(float4*)(hn + (size_t)idx * 4) = o;

    if (gidx > 0) {
        float g = gamma[gidx];
        float4 a = *(float4*)(g_acc + (size_t)idx * 4);
        a.x += g * v.x; a.y += g * v.y; a.z += g * v.z; a.w += g * v.w;
        *(float4*)(g_acc + (size_t)idx * 4) = a;
    }
}

// ---------------- propagation: edge scatter with vectorized reduction ----------------
__global__ void k_edge(int cur) {
    unsigned idx = blockIdx.x * blockDim.x + threadIdx.x;  // 8 threads per edge
    if (idx >= (unsigned)N_EDGES * 8u) return;
    const float* hc = cur ? g_h1 : g_h0;
    float* hn = cur ? g_h0 : g_h1;

    int e = (int)(idx >> 3);
    int q = ((int)idx & 7) * 4;
    int s = g_src[e];
    int d = g_dst[e];
    float nw = g_norm[e];
    float4 v = *(const float4*)(hc + (size_t)s * N_CLS + q);
    float rx = nw * v.x, ry = nw * v.y, rz = nw * v.z, rw = nw * v.w;
    float* p = hn + (size_t)d * N_CLS + q;
    asm volatile("red.global.add.v4.f32 [%0], {%1,%2,%3,%4};"
                 :: "l"(__cvta_generic_to_global(p)),
                    "f"(rx), "f"(ry), "f"(rz), "f"(rw) : "memory");
}

// ---------------- final: out = log_softmax(g_acc + gamma[K]*h_K) ----------------
__global__ void k_lsm(int cur, const float* __restrict__ gamma, float* __restrict__ out) {
    int tid = threadIdx.x;
    int warp = tid >> 5, lane = tid & 31;
    int n = blockIdx.x * 8 + warp;
    if (n >= N_NODES) return;
    const float* hlast = cur ? g_h1 : g_h0;

    float gK = gamma[KSTEPS];
    float v = g_acc[(size_t)n * N_CLS + lane] + gK * hlast[(size_t)n * N_CLS + lane];

    float m = v;
#pragma unroll
    for (int off = 16; off; off >>= 1)
        m = fmaxf(m, __shfl_xor_sync(0xffffffff, m, off));
    float e = expf(v - m);
    float sum = e;
#pragma unroll
    for (int off = 16; off; off >>= 1)
        sum += __shfl_xor_sync(0xffffffff, sum, off);
    out[(size_t)n * N_CLS + lane] = v - m - logf(sum);
}

// ---------------- launch ----------------
extern "C" void kernel_launch(void* const* d_in, const int* in_sizes, int n_in,
                              void* d_out, int out_size) {
    const float* x     = (const float*)d_in[0];
    const void*  eiraw = d_in[1];
    const float* W1    = (const float*)d_in[2];
    const float* b1    = (const float*)d_in[3];
    const float* W2    = (const float*)d_in[4];
    const float* b2    = (const float*)d_in[5];
    const float* gamma = (const float*)d_in[6];
    float*       out   = (float*)d_out;

    // edge index: sniff dtype, convert to int32 SoA
    k_sniff<<<1, 1>>>((const unsigned*)eiraw);
    k_cvt<<<(2 * N_EDGES + 255) / 256, 256>>>(eiraw);

    // degrees + edge norms (reused across all K steps)
    k_deg_init<<<(N_NODES + 255) / 256, 256>>>();
    k_deg_count<<<(N_EDGES + 255) / 256, 256>>>();
    k_deg_fin<<<(N_NODES + 255) / 256, 256>>>();
    k_norm<<<(N_EDGES + 255) / 256, 256>>>();

    // MLP
    dim3 g1(HID / 128, (N_NODES + 127) / 128);
    k_gemm1<<<g1, 256>>>(x, W1, b1);
    k_gemm2<<<(N_NODES + 7) / 8, 256>>>(W2, b2, gamma);

    // K propagation steps (ping-pong between g_h0/g_h1)
    int cur = 0;
    const int prepBlocks = (N_NODES * N_CLS / 4 + 255) / 256;
    const int edgeBlocks = (int)(((unsigned)N_EDGES * 8u + 255u) / 256u);
    for (int k = 1; k <= KSTEPS; k++) {
        k_prep<<<prepBlocks, 256>>>(cur, k - 1, gamma);   // gidx=0 on first step -> no axpy
        k_edge<<<edgeBlocks, 256>>>(cur);
        cur ^= 1;
    }

    k_lsm<<<(N_NODES + 7) / 8, 256>>>(cur, gamma, out);
}

// round 4
// speedup vs baseline: 1.4109x; 1.4109x over previous
#include <cuda_runtime.h>
#include <cuda_bf16.h>
#include <cstdint>

#define N_NODES 100000
#define F_IN    512
#define HID     256
#define N_CLS   32
#define N_EDGES 3200000
#define KSTEPS  10

// ---------------- device scratch ----------------
__device__ __align__(128) float g_z[(size_t)N_NODES * HID];
__device__ __align__(128) float g_h0[(size_t)N_NODES * N_CLS];
__device__ __align__(128) float g_h1[(size_t)N_NODES * N_CLS];
__device__ __align__(128) float g_acc[(size_t)N_NODES * N_CLS];
__device__ __align__(128) float g_dinv[N_NODES];
__device__ __align__(128) int   g_deg[N_NODES];
__device__ __align__(128) int   g_rowptr[N_NODES + 1];
__device__ __align__(128) int   g_pos[N_NODES];
__device__ __align__(128) int   g_src[N_EDGES];
__device__ __align__(128) int   g_dst[N_EDGES];
__device__ __align__(128) int   g_csr_src[N_EDGES];
__device__ __align__(128) float g_csr_w[N_EDGES];
__device__ __align__(128) __nv_bfloat16 g_x_hi[(size_t)N_NODES * F_IN];
__device__ __align__(128) __nv_bfloat16 g_x_lo[(size_t)N_NODES * F_IN];
__device__ __align__(128) __nv_bfloat16 g_w1t_hi[(size_t)HID * F_IN];
__device__ __align__(128) __nv_bfloat16 g_w1t_lo[(size_t)HID * F_IN];
__device__ int g_is64;

// ---------------- edge index dtype sniff + convert ----------------
__global__ void k_sniff(const unsigned* __restrict__ raw) {
    unsigned orv = 0;
#pragma unroll
    for (int i = 0; i < 16; i++) orv |= raw[2 * i + 1];
    g_is64 = (orv == 0u) ? 1 : 0;
}

__global__ void k_cvt(const void* __restrict__ raw) {
    int i = blockIdx.x * blockDim.x + threadIdx.x;
    if (i >= 2 * N_EDGES) return;
    int v;
    if (g_is64) v = (int)((const long long*)raw)[i];
    else        v = ((const int*)raw)[i];
    if (i < N_EDGES) g_src[i] = v;
    else             g_dst[i - N_EDGES] = v;
}

// ---------------- degree / dinv / CSR build ----------------
__global__ void k_deg_zero() {
    int i = blockIdx.x * blockDim.x + threadIdx.x;
    if (i < N_NODES) g_deg[i] = 0;
}

__global__ void k_deg_count() {
    int e = blockIdx.x * blockDim.x + threadIdx.x;
    if (e < N_EDGES) atomicAdd(&g_deg[g_dst[e]], 1);
}

__global__ void k_dinv() {
    int i = blockIdx.x * blockDim.x + threadIdx.x;
    if (i < N_NODES) g_dinv[i] = rsqrtf(1.0f + (float)g_deg[i]);  // +1 self-loop
}

__global__ __launch_bounds__(1024) void k_scan() {
    __shared__ int warpsum[32];
    __shared__ int carry_s;
    const int tid = threadIdx.x;
    const int lane = tid & 31, w = tid >> 5;
    if (tid == 0) carry_s = 0;
    __syncthreads();
    for (int base = 0; base < N_NODES; base += 1024) {
        int i = base + tid;
        int v = (i < N_NODES) ? g_deg[i] : 0;
        int x = v;
#pragma unroll
        for (int o = 1; o < 32; o <<= 1) {
            int t = __shfl_up_sync(0xffffffffu, x, o);
            if (lane >= o) x += t;
        }
        if (lane == 31) warpsum[w] = x;
        __syncthreads();
        if (tid < 32) {
            int y = warpsum[tid];
#pragma unroll
            for (int o = 1; o < 32; o <<= 1) {
                int t = __shfl_up_sync(0xffffffffu, y, o);
                if (tid >= o) y += t;
            }
            warpsum[tid] = y;
        }
        __syncthreads();
        int pre = (w > 0) ? warpsum[w - 1] : 0;
        int excl = carry_s + pre + (x - v);
        if (i < N_NODES) { g_rowptr[i] = excl; g_pos[i] = excl; }
        int btotal = warpsum[31];
        __syncthreads();
        if (tid == 0) carry_s += btotal;
        __syncthreads();
    }
    if (tid == 0) g_rowptr[N_NODES] = carry_s;
}

__global__ void k_fill() {
    int e = blockIdx.x * blockDim.x + threadIdx.x;
    if (e >= N_EDGES) return;
    int s = g_src[e], d = g_dst[e];
    float wv = g_dinv[s] * g_dinv[d];
    int p = atomicAdd(&g_pos[d], 1);
    g_csr_src[p] = s;
    g_csr_w[p] = wv;
}

// ---------------- fp32 -> bf16 hi/lo conversions ----------------
__global__ void k_xcvt(const float* __restrict__ x) {
    size_t i = (size_t)blockIdx.x * blockDim.x + threadIdx.x;   // one float4
    if (i >= (size_t)N_NODES * F_IN / 4) return;
    float4 v = ((const float4*)x)[i];
    __nv_bfloat16 h0 = __float2bfloat16(v.x), h1 = __float2bfloat16(v.y);
    __nv_bfloat16 h2 = __float2bfloat16(v.z), h3 = __float2bfloat16(v.w);
    __nv_bfloat16 l0 = __float2bfloat16(v.x - __bfloat162float(h0));
    __nv_bfloat16 l1 = __float2bfloat16(v.y - __bfloat162float(h1));
    __nv_bfloat16 l2 = __float2bfloat16(v.z - __bfloat162float(h2));
    __nv_bfloat16 l3 = __float2bfloat16(v.w - __bfloat162float(h3));
    uint2 ph, pl;
    ph.x = (uint32_t)__bfloat16_as_ushort(h0) | ((uint32_t)__bfloat16_as_ushort(h1) << 16);
    ph.y = (uint32_t)__bfloat16_as_ushort(h2) | ((uint32_t)__bfloat16_as_ushort(h3) << 16);
    pl.x = (uint32_t)__bfloat16_as_ushort(l0) | ((uint32_t)__bfloat16_as_ushort(l1) << 16);
    pl.y = (uint32_t)__bfloat16_as_ushort(l2) | ((uint32_t)__bfloat16_as_ushort(l3) << 16);
    ((uint2*)g_x_hi)[i] = ph;
    ((uint2*)g_x_lo)[i] = pl;
}

__global__ void k_w1cvt(const float* __restrict__ W1) {
    int i = blockIdx.x * blockDim.x + threadIdx.x;
    if (i >= F_IN * HID) return;
    int k = i / HID, n = i % HID;
    float v = W1[i];
    __nv_bfloat16 h = __float2bfloat16(v);
    g_w1t_hi[(size_t)n * F_IN + k] = h;
    g_w1t_lo[(size_t)n * F_IN + k] = __float2bfloat16(v - __bfloat162float(h));
}

// ---------------- GEMM1 via mma.sync bf16 split: g_z = relu(x @ W1 + b1) ----------------
#define SMSTRIDE 72
#define AS_HI_O  0u
#define AS_LO_O  18432u
#define BS_HI_O  36864u
#define BS_LO_O  55296u
#define BIAS_O   73728u
#define G1_SMEM  74240u

#define MMA16816(c, a, b) \
    asm volatile("mma.sync.aligned.m16n8k16.row.col.f32.bf16.bf16.f32 " \
                 "{%0,%1,%2,%3},{%4,%5,%6,%7},{%8,%9},{%0,%1,%2,%3};" \
                 : "+f"((c)[0]), "+f"((c)[1]), "+f"((c)[2]), "+f"((c)[3]) \
                 : "r"((a)[0]), "r"((a)[1]), "r"((a)[2]), "r"((a)[3]), \
                   "r"((b)[0]), "r"((b)[1]))

__global__ __launch_bounds__(256, 1) void k_gemm1_mma(const float* __restrict__ b1) {
    extern __shared__ __align__(16) char sm[];
    __nv_bfloat16* as_hi = (__nv_bfloat16*)(sm + AS_HI_O);
    __nv_bfloat16* as_lo = (__nv_bfloat16*)(sm + AS_LO_O);
    __nv_bfloat16* bs_hi = (__nv_bfloat16*)(sm + BS_HI_O);
    __nv_bfloat16* bs_lo = (__nv_bfloat16*)(sm + BS_LO_O);
    float* bias_s = (float*)(sm + BIAS_O);

    const int tid = threadIdx.x;
    const int wid = tid >> 5, lane = tid & 31;
    const int g = lane >> 2, tg = lane & 3;
    const int rowBase = blockIdx.x * 128;
    const int colBase = blockIdx.y * 128;
    const int wr = (wid >> 2) * 64, wc = (wid & 3) * 32;

    if (tid < 128) bias_s[tid] = b1[colBase + tid];

    float acc[4][4][4];
#pragma unroll
    for (int a = 0; a < 4; a++)
#pragma unroll
        for (int b = 0; b < 4; b++)
#pragma unroll
            for (int c = 0; c < 4; c++) acc[a][b][c] = 0.f;

    for (int k0 = 0; k0 < F_IN; k0 += 64) {
        __syncthreads();
        // A tile: 128 rows x 64 k, bf16 hi/lo (uint4 = 8 bf16)
        for (int i = tid; i < 1024; i += 256) {
            int r = i >> 3, k8 = (i & 7) * 8;
            uint4 vh = make_uint4(0, 0, 0, 0), vl = make_uint4(0, 0, 0, 0);
            int grow = rowBase + r;
            if (grow < N_NODES) {
                size_t gi = (size_t)grow * F_IN + k0 + k8;
                vh = *(const uint4*)(g_x_hi + gi);
                vl = *(const uint4*)(g_x_lo + gi);
            }
            *(uint4*)(as_hi + r * SMSTRIDE + k8) = vh;
            *(uint4*)(as_lo + r * SMSTRIDE + k8) = vl;
        }
        // B tile: 128 n-rows x 64 k
        for (int i = tid; i < 1024; i += 256) {
            int n = i >> 3, k8 = (i & 7) * 8;
            size_t gi = (size_t)(colBase + n) * F_IN + k0 + k8;
            *(uint4*)(bs_hi + n * SMSTRIDE + k8) = *(const uint4*)(g_w1t_hi + gi);
            *(uint4*)(bs_lo + n * SMSTRIDE + k8) = *(const uint4*)(g_w1t_lo + gi);
        }
        __syncthreads();

#pragma unroll
        for (int ks = 0; ks < 4; ks++) {
            const int ko = ks * 16;
            uint32_t ah[4][4], al[4][4], bh[4][2], bl[4][2];
#pragma unroll
            for (int mt = 0; mt < 4; mt++) {
                int r0 = wr + mt * 16 + g;
                ah[mt][0] = *(const uint32_t*)(as_hi + r0 * SMSTRIDE + ko + 2 * tg);
                ah[mt][1] = *(const uint32_t*)(as_hi + (r0 + 8) * SMSTRIDE + ko + 2 * tg);
                ah[mt][2] = *(const uint32_t*)(as_hi + r0 * SMSTRIDE + ko + 8 + 2 * tg);
                ah[mt][3] = *(const uint32_t*)(as_hi + (r0 + 8) * SMSTRIDE + ko + 8 + 2 * tg);
                al[mt][0] = *(const uint32_t*)(as_lo + r0 * SMSTRIDE + ko + 2 * tg);
                al[mt][1] = *(const uint32_t*)(as_lo + (r0 + 8) * SMSTRIDE + ko + 2 * tg);
                al[mt][2] = *(const uint32_t*)(as_lo + r0 * SMSTRIDE + ko + 8 + 2 * tg);
                al[mt][3] = *(const uint32_t*)(as_lo + (r0 + 8) * SMSTRIDE + ko + 8 + 2 * tg);
            }
#pragma unroll
            for (int nt = 0; nt < 4; nt++) {
                int n0 = wc + nt * 8 + g;
                bh[nt][0] = *(const uint32_t*)(bs_hi + n0 * SMSTRIDE + ko + 2 * tg);
                bh[nt][1] = *(const uint32_t*)(bs_hi + n0 * SMSTRIDE + ko + 8 + 2 * tg);
                bl[nt][0] = *(const uint32_t*)(bs_lo + n0 * SMSTRIDE + ko + 2 * tg);
                bl[nt][1] = *(const uint32_t*)(bs_lo + n0 * SMSTRIDE + ko + 8 + 2 * tg);
            }
#pragma unroll
            for (int mt = 0; mt < 4; mt++)
#pragma unroll
                for (int nt = 0; nt < 4; nt++) {
                    MMA16816(acc[mt][nt], ah[mt], bh[nt]);
                    MMA16816(acc[mt][nt], ah[mt], bl[nt]);
                    MMA16816(acc[mt][nt], al[mt], bh[nt]);
                }
        }
    }

    // epilogue: bias + relu
#pragma unroll
    for (int mt = 0; mt < 4; mt++) {
        int r0 = rowBase + wr + mt * 16 + g;
        int r1 = r0 + 8;
#pragma unroll
        for (int nt = 0; nt < 4; nt++) {
            int cl = wc + nt * 8 + 2 * tg;
            float bx = bias_s[cl], by = bias_s[cl + 1];
            if (r0 < N_NODES) {
                float2 o;
                o.x = fmaxf(acc[mt][nt][0] + bx, 0.f);
                o.y = fmaxf(acc[mt][nt][1] + by, 0.f);
                *(float2*)(g_z + (size_t)r0 * HID + colBase + cl) = o;
            }
            if (r1 < N_NODES) {
                float2 o;
                o.x = fmaxf(acc[mt][nt][2] + bx, 0.f);
                o.y = fmaxf(acc[mt][nt][3] + by, 0.f);
                *(float2*)(g_z + (size_t)r1 * HID + colBase + cl) = o;
            }
        }
    }
}

// ---------------- GEMM2: g_h0 = g_z @ W2 + b2 ; g_acc = gamma[0]*g_h0 ----------------
__global__ __launch_bounds__(256) void k_gemm2(const float* __restrict__ W2,
                                               const float* __restrict__ b2,
                                               const float* __restrict__ gamma) {
    __shared__ __align__(16) float w2s[HID * N_CLS];
    __shared__ __align__(16) float zs[8 * HID];

    const int tid = threadIdx.x;
    for (int i = tid; i < HID * N_CLS; i += 256) w2s[i] = W2[i];

    const int rowBase = blockIdx.x * 8;
    for (int i = tid; i < 8 * HID; i += 256) {
        int r = rowBase + (i >> 8);
        zs[i] = (r < N_NODES) ? g_z[(size_t)r * HID + (i & 255)] : 0.f;
    }
    __syncthreads();

    const int r = tid >> 5;
    const int c = tid & 31;
    float s = b2[c];
#pragma unroll 8
    for (int k = 0; k < HID; k++)
        s += zs[r * HID + k] * w2s[k * N_CLS + c];

    int row = rowBase + r;
    if (row < N_NODES) {
        size_t o = (size_t)row * N_CLS + c;
        g_h0[o] = s;
        g_acc[o] = gamma[0] * s;
    }
}

// ---------------- SpMV step: hn = A_hat * hc ; g_acc += gamma[gi]*hn ----------------
__global__ __launch_bounds__(256) void k_spmv(int cur, int gi, const float* __restrict__ gamma) {
    const float* hc = cur ? g_h1 : g_h0;
    float* hn = cur ? g_h0 : g_h1;

    int warp = (blockIdx.x * blockDim.x + threadIdx.x) >> 5;
    int lane = threadIdx.x & 31;
    if (warp >= N_NODES) return;
    int n = warp;
    int beg = g_rowptr[n], end = g_rowptr[n + 1];
    float di = g_dinv[n];
    float acc = di * di * hc[(size_t)n * N_CLS + lane];   // self-loop

    for (int e0 = beg; e0 < end; e0 += 32) {
        int ee = e0 + lane;
        int s = 0; float w = 0.f;
        if (ee < end) { s = g_csr_src[ee]; w = g_csr_w[ee]; }
        int cnt = end - e0; if (cnt > 32) cnt = 32;
        int i = 0;
        for (; i + 4 <= cnt; i += 4) {
            int s0 = __shfl_sync(0xffffffffu, s, i);
            int s1 = __shfl_sync(0xffffffffu, s, i + 1);
            int s2 = __shfl_sync(0xffffffffu, s, i + 2);
            int s3 = __shfl_sync(0xffffffffu, s, i + 3);
            float w0 = __shfl_sync(0xffffffffu, w, i);
            float w1 = __shfl_sync(0xffffffffu, w, i + 1);
            float w2 = __shfl_sync(0xffffffffu, w, i + 2);
            float w3 = __shfl_sync(0xffffffffu, w, i + 3);
            float v0 = hc[(size_t)s0 * N_CLS + lane];
            float v1 = hc[(size_t)s1 * N_CLS + lane];
            float v2 = hc[(size_t)s2 * N_CLS + lane];
            float v3 = hc[(size_t)s3 * N_CLS + lane];
            acc += w0 * v0; acc += w1 * v1; acc += w2 * v2; acc += w3 * v3;
        }
        for (; i < cnt; i++) {
            int si = __shfl_sync(0xffffffffu, s, i);
            float wi = __shfl_sync(0xffffffffu, w, i);
            acc += wi * hc[(size_t)si * N_CLS + lane];
        }
    }

    size_t o = (size_t)n * N_CLS + lane;
    hn[o] = acc;
    g_acc[o] += gamma[gi] * acc;
}

// ---------------- final: out = log_softmax(g_acc) ----------------
__global__ void k_lsm(float* __restrict__ out) {
    int tid = threadIdx.x;
    int warp = tid >> 5, lane = tid & 31;
    int n = blockIdx.x * 8 + warp;
    if (n >= N_NODES) return;

    float v = g_acc[(size_t)n * N_CLS + lane];
    float m = v;
#pragma unroll
    for (int off = 16; off; off >>= 1)
        m = fmaxf(m, __shfl_xor_sync(0xffffffffu, m, off));
    float e = expf(v - m);
    float sum = e;
#pragma unroll
    for (int off = 16; off; off >>= 1)
        sum += __shfl_xor_sync(0xffffffffu, sum, off);
    out[(size_t)n * N_CLS + lane] = v - m - logf(sum);
}

// ---------------- launch ----------------
extern "C" void kernel_launch(void* const* d_in, const int* in_sizes, int n_in,
                              void* d_out, int out_size) {
    const float* x     = (const float*)d_in[0];
    const void*  eiraw = d_in[1];
    const float* W1    = (const float*)d_in[2];
    const float* b1    = (const float*)d_in[3];
    const float* W2    = (const float*)d_in[4];
    const float* b2    = (const float*)d_in[5];
    const float* gamma = (const float*)d_in[6];
    float*       out   = (float*)d_out;

    // edge index: sniff dtype, convert to int32 SoA
    k_sniff<<<1, 1>>>((const unsigned*)eiraw);
    k_cvt<<<(2 * N_EDGES + 255) / 256, 256>>>(eiraw);

    // degrees, dinv, CSR
    k_deg_zero<<<(N_NODES + 255) / 256, 256>>>();
    k_deg_count<<<(N_EDGES + 255) / 256, 256>>>();
    k_dinv<<<(N_NODES + 255) / 256, 256>>>();
    k_scan<<<1, 1024>>>();
    k_fill<<<(N_EDGES + 255) / 256, 256>>>();

    // MLP
    k_xcvt<<<(int)(((size_t)N_NODES * F_IN / 4 + 255) / 256), 256>>>(x);
    k_w1cvt<<<(F_IN * HID + 255) / 256, 256>>>(W1);
    cudaFuncSetAttribute(k_gemm1_mma, cudaFuncAttributeMaxDynamicSharedMemorySize, G1_SMEM);
    dim3 g1((N_NODES + 127) / 128, HID / 128);
    k_gemm1_mma<<<g1, 256, G1_SMEM>>>(b1);
    k_gemm2<<<(N_NODES + 7) / 8, 256>>>(W2, b2, gamma);

    // K propagation steps
    int cur = 0;
    for (int k = 1; k <= KSTEPS; k++) {
        k_spmv<<<(N_NODES + 7) / 8, 256>>>(cur, k, gamma);
        cur ^= 1;
    }

    k_lsm<<<(N_NODES + 7) / 8, 256>>>(out);
}

// round 6
// speedup vs baseline: 1.7231x; 1.2212x over previous
#include <cuda_runtime.h>
#include <cuda_bf16.h>
#include <cstdint>

#define N_NODES 100000
#define F_IN    512
#define HID     256
#define N_CLS   32
#define N_EDGES 3200000
#define KSTEPS  10

// ---------------- device scratch ----------------
__device__ __align__(128) float g_h0[(size_t)N_NODES * N_CLS];
__device__ __align__(128) float g_h1[(size_t)N_NODES * N_CLS];
__device__ __align__(128) float g_acc[(size_t)N_NODES * N_CLS];
__device__ __align__(128) float g_dinv[N_NODES];
__device__ __align__(128) int   g_deg[N_NODES];
__device__ __align__(128) int   g_rowptr[N_NODES + 1];
__device__ __align__(128) int   g_pos[N_NODES];
__device__ __align__(128) int   g_src[N_EDGES];
__device__ __align__(128) int   g_dst[N_EDGES];
__device__ __align__(128) int2  g_csr[N_EDGES];
__device__ __align__(128) __nv_bfloat16 g_w1t_hi[(size_t)HID * F_IN];
__device__ __align__(128) __nv_bfloat16 g_w1t_lo[(size_t)HID * F_IN];
__device__ __align__(128) __nv_bfloat16 g_w2t_hi[(size_t)N_CLS * HID];
__device__ __align__(128) __nv_bfloat16 g_w2t_lo[(size_t)N_CLS * HID];
__device__ int g_is64;

// ---------------- edge index dtype sniff + convert (+deg count fused) ----------------
__global__ void k_sniff(const unsigned* __restrict__ raw) {
    unsigned orv = 0;
#pragma unroll
    for (int i = 0; i < 16; i++) orv |= raw[2 * i + 1];
    g_is64 = (orv == 0u) ? 1 : 0;
}

__global__ void k_cvt(const void* __restrict__ raw) {
    int i = blockIdx.x * blockDim.x + threadIdx.x;
    if (i >= 2 * N_EDGES) return;
    int v;
    if (g_is64) v = (int)((const long long*)raw)[i];
    else        v = ((const int*)raw)[i];
    if (i < N_EDGES) g_src[i] = v;
    else { g_dst[i - N_EDGES] = v; atomicAdd(&g_deg[v], 1); }
}

__global__ void k_deg_zero() {
    int i = blockIdx.x * blockDim.x + threadIdx.x;
    if (i < N_NODES) g_deg[i] = 0;
}

__global__ void k_dinv() {
    int i = blockIdx.x * blockDim.x + threadIdx.x;
    if (i < N_NODES) g_dinv[i] = rsqrtf(1.0f + (float)g_deg[i]);
}

__global__ __launch_bounds__(1024) void k_scan() {
    __shared__ int warpsum[32];
    __shared__ int carry_s;
    const int tid = threadIdx.x;
    const int lane = tid & 31, w = tid >> 5;
    if (tid == 0) carry_s = 0;
    __syncthreads();
    for (int base = 0; base < N_NODES; base += 1024) {
        int i = base + tid;
        int v = (i < N_NODES) ? g_deg[i] : 0;
        int x = v;
#pragma unroll
        for (int o = 1; o < 32; o <<= 1) {
            int t = __shfl_up_sync(0xffffffffu, x, o);
            if (lane >= o) x += t;
        }
        if (lane == 31) warpsum[w] = x;
        __syncthreads();
        if (tid < 32) {
            int y = warpsum[tid];
#pragma unroll
            for (int o = 1; o < 32; o <<= 1) {
                int t = __shfl_up_sync(0xffffffffu, y, o);
                if (tid >= o) y += t;
            }
            warpsum[tid] = y;
        }
        __syncthreads();
        int pre = (w > 0) ? warpsum[w - 1] : 0;
        int excl = carry_s + pre + (x - v);
        if (i < N_NODES) { g_rowptr[i] = excl; g_pos[i] = excl; }
        int btotal = warpsum[31];
        __syncthreads();
        if (tid == 0) carry_s += btotal;
        __syncthreads();
    }
    if (tid == 0) g_rowptr[N_NODES] = carry_s;
}

__global__ void k_fill() {
    int e = blockIdx.x * blockDim.x + threadIdx.x;
    if (e >= N_EDGES) return;
    int s = g_src[e], d = g_dst[e];
    float wv = g_dinv[s] * g_dinv[d];
    int p = atomicAdd(&g_pos[d], 1);
    g_csr[p] = make_int2(s, __float_as_int(wv));
}

// ---------------- weight conversions ----------------
__global__ void k_w1cvt(const float* __restrict__ W1) {
    int i = blockIdx.x * blockDim.x + threadIdx.x;
    if (i >= F_IN * HID) return;
    int k = i / HID, n = i % HID;
    float v = W1[i];
    __nv_bfloat16 h = __float2bfloat16(v);
    g_w1t_hi[(size_t)n * F_IN + k] = h;
    g_w1t_lo[(size_t)n * F_IN + k] = __float2bfloat16(v - __bfloat162float(h));
}

__global__ void k_w2cvt(const float* __restrict__ W2) {
    int i = blockIdx.x * blockDim.x + threadIdx.x;
    if (i >= HID * N_CLS) return;
    int k = i / N_CLS, n = i % N_CLS;
    float v = W2[i];
    __nv_bfloat16 h = __float2bfloat16(v);
    g_w2t_hi[(size_t)n * HID + k] = h;
    g_w2t_lo[(size_t)n * HID + k] = __float2bfloat16(v - __bfloat162float(h));
}

// ---------------- fused MLP: h0 = relu(x@W1+b1)@W2 + b2 ; acc = gamma0*h0 ----------------
#define ST1  72      // phase1 smem stride (bf16 elems)
#define ST2  264     // phase2 smem stride (bf16 elems)

#define ASH_O   0u
#define ASL_O   18432u
#define BSH_O   36864u
#define BSL_O   73728u
#define ZHI_O   0u
#define ZLO_O   67584u
#define W2HI_O  135168u
#define W2LO_O  152064u
#define B2_O    168960u
#define BIAS_O  169088u
#define SMEM_T  170112u

#define MMA16816(c, a, b) \
    asm volatile("mma.sync.aligned.m16n8k16.row.col.f32.bf16.bf16.f32 " \
                 "{%0,%1,%2,%3},{%4,%5,%6,%7},{%8,%9},{%0,%1,%2,%3};" \
                 : "+f"((c)[0]), "+f"((c)[1]), "+f"((c)[2]), "+f"((c)[3]) \
                 : "r"((a)[0]), "r"((a)[1]), "r"((a)[2]), "r"((a)[3]), \
                   "r"((b)[0]), "r"((b)[1]))

__device__ __forceinline__ uint32_t pack_hi(float a, float b) {
    __nv_bfloat16 h0 = __float2bfloat16(a), h1 = __float2bfloat16(b);
    return (uint32_t)__bfloat16_as_ushort(h0) | ((uint32_t)__bfloat16_as_ushort(h1) << 16);
}
__device__ __forceinline__ uint32_t pack_lo(float a, float b) {
    __nv_bfloat16 h0 = __float2bfloat16(a), h1 = __float2bfloat16(b);
    float r0 = a - __bfloat162float(h0), r1 = b - __bfloat162float(h1);
    __nv_bfloat16 l0 = __float2bfloat16(r0), l1 = __float2bfloat16(r1);
    return (uint32_t)__bfloat16_as_ushort(l0) | ((uint32_t)__bfloat16_as_ushort(l1) << 16);
}

__global__ __launch_bounds__(256, 1) void k_mlp(const float* __restrict__ x,
                                                const float* __restrict__ b1,
                                                const float* __restrict__ b2,
                                                const float* __restrict__ gamma) {
    extern __shared__ __align__(16) char sm[];
    __nv_bfloat16* as_hi = (__nv_bfloat16*)(sm + ASH_O);
    __nv_bfloat16* as_lo = (__nv_bfloat16*)(sm + ASL_O);
    __nv_bfloat16* bs_hi = (__nv_bfloat16*)(sm + BSH_O);
    __nv_bfloat16* bs_lo = (__nv_bfloat16*)(sm + BSL_O);
    uint32_t* zhi = (uint32_t*)(sm + ZHI_O);     // word idx = r*132 + c/2
    uint32_t* zlo = (uint32_t*)(sm + ZLO_O);
    __nv_bfloat16* w2hi = (__nv_bfloat16*)(sm + W2HI_O);
    __nv_bfloat16* w2lo = (__nv_bfloat16*)(sm + W2LO_O);
    float* b2s = (float*)(sm + B2_O);
    float* bias_s = (float*)(sm + BIAS_O);

    const int tid = threadIdx.x;
    const int wid = tid >> 5, lane = tid & 31;
    const int gq = lane >> 2, tg = lane & 3;
    const int rowBase = blockIdx.x * 128;
    const int wr = (wid >> 2) * 64, wc = (wid & 3) * 64;

    bias_s[tid] = b1[tid];
    if (tid < N_CLS) b2s[tid] = b2[tid];
    // W2^T hi/lo into smem (32 x 256)
    for (int i = tid; i < 1024; i += 256) {
        int n = i >> 5, k8 = (i & 31) * 8;
        *(uint4*)(w2hi + n * ST2 + k8) = *(const uint4*)(g_w2t_hi + n * HID + k8);
        *(uint4*)(w2lo + n * ST2 + k8) = *(const uint4*)(g_w2t_lo + n * HID + k8);
    }

    float acc[4][8][4];
#pragma unroll
    for (int a = 0; a < 4; a++)
#pragma unroll
        for (int b = 0; b < 8; b++)
#pragma unroll
            for (int c = 0; c < 4; c++) acc[a][b][c] = 0.f;

    for (int ch = 0; ch < 8; ch++) {
        const int k0 = ch * 64;
        __syncthreads();
        // A tile 128x64: load fp32, convert in-kernel
        for (int i = tid; i < 2048; i += 256) {
            int r = i >> 4, cc = (i & 15) * 4;
            float4 v = make_float4(0.f, 0.f, 0.f, 0.f);
            int grow = rowBase + r;
            if (grow < N_NODES)
                v = *(const float4*)(x + (size_t)grow * F_IN + k0 + cc);
            uint2 ph = make_uint2(pack_hi(v.x, v.y), pack_hi(v.z, v.w));
            uint2 pl = make_uint2(pack_lo(v.x, v.y), pack_lo(v.z, v.w));
            *(uint2*)(as_hi + r * ST1 + cc) = ph;
            *(uint2*)(as_lo + r * ST1 + cc) = pl;
        }
        // B tile 256x64 from preconverted W1^T
        for (int i = tid; i < 2048; i += 256) {
            int n = i >> 3, k8 = (i & 7) * 8;
            size_t gi = (size_t)n * F_IN + k0 + k8;
            *(uint4*)(bs_hi + n * ST1 + k8) = *(const uint4*)(g_w1t_hi + gi);
            *(uint4*)(bs_lo + n * ST1 + k8) = *(const uint4*)(g_w1t_lo + gi);
        }
        __syncthreads();

#pragma unroll
        for (int ks = 0; ks < 4; ks++) {
            const int ko = ks * 16;
            uint32_t ah[4][4], al[4][4];
#pragma unroll
            for (int mt = 0; mt < 4; mt++) {
                int r0 = wr + mt * 16 + gq;
                ah[mt][0] = *(const uint32_t*)(as_hi + r0 * ST1 + ko + 2 * tg);
                ah[mt][1] = *(const uint32_t*)(as_hi + (r0 + 8) * ST1 + ko + 2 * tg);
                ah[mt][2] = *(const uint32_t*)(as_hi + r0 * ST1 + ko + 8 + 2 * tg);
                ah[mt][3] = *(const uint32_t*)(as_hi + (r0 + 8) * ST1 + ko + 8 + 2 * tg);
                al[mt][0] = *(const uint32_t*)(as_lo + r0 * ST1 + ko + 2 * tg);
                al[mt][1] = *(const uint32_t*)(as_lo + (r0 + 8) * ST1 + ko + 2 * tg);
                al[mt][2] = *(const uint32_t*)(as_lo + r0 * ST1 + ko + 8 + 2 * tg);
                al[mt][3] = *(const uint32_t*)(as_lo + (r0 + 8) * ST1 + ko + 8 + 2 * tg);
            }
#pragma unroll
            for (int nt = 0; nt < 8; nt++) {
                int n0 = wc + nt * 8 + gq;
                uint32_t bh[2], bl[2];
                bh[0] = *(const uint32_t*)(bs_hi + n0 * ST1 + ko + 2 * tg);
                bh[1] = *(const uint32_t*)(bs_hi + n0 * ST1 + ko + 8 + 2 * tg);
                bl[0] = *(const uint32_t*)(bs_lo + n0 * ST1 + ko + 2 * tg);
                bl[1] = *(const uint32_t*)(bs_lo + n0 * ST1 + ko + 8 + 2 * tg);
#pragma unroll
                for (int mt = 0; mt < 4; mt++) {
                    MMA16816(acc[mt][nt], ah[mt], bh);
                    MMA16816(acc[mt][nt], ah[mt], bl);
                    MMA16816(acc[mt][nt], al[mt], bh);
                }
            }
        }
    }

    __syncthreads();   // all MMAs done before smem reuse

    // epilogue phase1: bias+relu -> z bf16 hi/lo in smem
#pragma unroll
    for (int mt = 0; mt < 4; mt++) {
        int r0 = wr + mt * 16 + gq;
        int r1 = r0 + 8;
#pragma unroll
        for (int nt = 0; nt < 8; nt++) {
            int cl = wc + nt * 8 + 2 * tg;
            float bx = bias_s[cl], by = bias_s[cl + 1];
            float o0 = fmaxf(acc[mt][nt][0] + bx, 0.f);
            float o1 = fmaxf(acc[mt][nt][1] + by, 0.f);
            float o2 = fmaxf(acc[mt][nt][2] + bx, 0.f);
            float o3 = fmaxf(acc[mt][nt][3] + by, 0.f);
            int w0 = r0 * 132 + (cl >> 1);
            int w1 = r1 * 132 + (cl >> 1);
            zhi[w0] = pack_hi(o0, o1); zlo[w0] = pack_lo(o0, o1);
            zhi[w1] = pack_hi(o2, o3); zlo[w1] = pack_lo(o2, o3);
        }
    }
    __syncthreads();

    // phase2: h0 = z @ W2 + b2 ; acc = gamma[0]*h0   (each warp: 16 rows x 32 cols)
    float acc2[4][4];
#pragma unroll
    for (int a = 0; a < 4; a++)
#pragma unroll
        for (int c = 0; c < 4; c++) acc2[a][c] = 0.f;

    const int rl0 = wid * 16 + gq;
#pragma unroll
    for (int ks = 0; ks < 16; ks++) {
        const int kw = ks * 8 + tg;   // word offset along k
        uint32_t ah[4], al[4];
        ah[0] = zhi[rl0 * 132 + kw];
        ah[1] = zhi[(rl0 + 8) * 132 + kw];
        ah[2] = zhi[rl0 * 132 + kw + 4];
        ah[3] = zhi[(rl0 + 8) * 132 + kw + 4];
        al[0] = zlo[rl0 * 132 + kw];
        al[1] = zlo[(rl0 + 8) * 132 + kw];
        al[2] = zlo[rl0 * 132 + kw + 4];
        al[3] = zlo[(rl0 + 8) * 132 + kw + 4];
#pragma unroll
        for (int nt = 0; nt < 4; nt++) {
            int n0 = nt * 8 + gq;
            uint32_t bh[2], bl[2];
            bh[0] = *(const uint32_t*)(w2hi + n0 * ST2 + ks * 16 + 2 * tg);
            bh[1] = *(const uint32_t*)(w2hi + n0 * ST2 + ks * 16 + 8 + 2 * tg);
            bl[0] = *(const uint32_t*)(w2lo + n0 * ST2 + ks * 16 + 2 * tg);
            bl[1] = *(const uint32_t*)(w2lo + n0 * ST2 + ks * 16 + 8 + 2 * tg);
            MMA16816(acc2[nt], ah, bh);
            MMA16816(acc2[nt], ah, bl);
            MMA16816(acc2[nt], al, bh);
        }
    }

    float g0 = gamma[0];
    int row0 = rowBase + rl0, row1 = row0 + 8;
#pragma unroll
    for (int nt = 0; nt < 4; nt++) {
        int cl = nt * 8 + 2 * tg;
        float bx = b2s[cl], by = b2s[cl + 1];
        if (row0 < N_NODES) {
            float2 h = make_float2(acc2[nt][0] + bx, acc2[nt][1] + by);
            *(float2*)(g_h0 + (size_t)row0 * N_CLS + cl) = h;
            *(float2*)(g_acc + (size_t)row0 * N_CLS + cl) = make_float2(g0 * h.x, g0 * h.y);
        }
        if (row1 < N_NODES) {
            float2 h = make_float2(acc2[nt][2] + bx, acc2[nt][3] + by);
            *(float2*)(g_h0 + (size_t)row1 * N_CLS + cl) = h;
            *(float2*)(g_acc + (size_t)row1 * N_CLS + cl) = make_float2(g0 * h.x, g0 * h.y);
        }
    }
}

// ---------------- SpMV step: hn = A_hat * hc ; g_acc += gamma[gi]*hn ----------------
__global__ __launch_bounds__(256) void k_spmv(int cur, int gi, const float* __restrict__ gamma) {
    __shared__ __align__(16) int2 est[8][32];
    const float* hc = cur ? g_h1 : g_h0;
    float* hn = cur ? g_h0 : g_h1;

    const int wslot = threadIdx.x >> 5;
    int warp = (blockIdx.x * blockDim.x + threadIdx.x) >> 5;
    int lane = threadIdx.x & 31;
    if (warp >= N_NODES) return;
    int n = warp;
    int beg = g_rowptr[n], end = g_rowptr[n + 1];
    float di = g_dinv[n];
    float acc = di * di * hc[(size_t)n * N_CLS + lane];

    for (int e0 = beg; e0 < end; e0 += 32) {
        int ee = e0 + lane;
        if (ee < end) est[wslot][lane] = g_csr[ee];
        __syncwarp();
        int cnt = end - e0; if (cnt > 32) cnt = 32;
        int i = 0;
        for (; i + 4 <= cnt; i += 4) {
            int2 e0v = est[wslot][i];
            int2 e1v = est[wslot][i + 1];
            int2 e2v = est[wslot][i + 2];
            int2 e3v = est[wslot][i + 3];
            float v0 = hc[(size_t)e0v.x * N_CLS + lane];
            float v1 = hc[(size_t)e1v.x * N_CLS + lane];
            float v2 = hc[(size_t)e2v.x * N_CLS + lane];
            float v3 = hc[(size_t)e3v.x * N_CLS + lane];
            acc += __int_as_float(e0v.y) * v0;
            acc += __int_as_float(e1v.y) * v1;
            acc += __int_as_float(e2v.y) * v2;
            acc += __int_as_float(e3v.y) * v3;
        }
        for (; i < cnt; i++) {
            int2 ev = est[wslot][i];
            acc += __int_as_float(ev.y) * hc[(size_t)ev.x * N_CLS + lane];
        }
        __syncwarp();
    }

    size_t o = (size_t)n * N_CLS + lane;
    hn[o] = acc;
    g_acc[o] += gamma[gi] * acc;
}

// ---------------- final: out = log_softmax(g_acc) ----------------
__global__ void k_lsm(float* __restrict__ out) {
    int tid = threadIdx.x;
    int warp = tid >> 5, lane = tid & 31;
    int n = blockIdx.x * 8 + warp;
    if (n >= N_NODES) return;

    float v = g_acc[(size_t)n * N_CLS + lane];
    float m = v;
#pragma unroll
    for (int off = 16; off; off >>= 1)
        m = fmaxf(m, __shfl_xor_sync(0xffffffffu, m, off));
    float e = expf(v - m);
    float sum = e;
#pragma unroll
    for (int off = 16; off; off >>= 1)
        sum += __shfl_xor_sync(0xffffffffu, sum, off);
    out[(size_t)n * N_CLS + lane] = v - m - logf(sum);
}

// ---------------- launch ----------------
extern "C" void kernel_launch(void* const* d_in, const int* in_sizes, int n_in,
                              void* d_out, int out_size) {
    const float* x     = (const float*)d_in[0];
    const void*  eiraw = d_in[1];
    const float* W1    = (const float*)d_in[2];
    const float* b1    = (const float*)d_in[3];
    const float* W2    = (const float*)d_in[4];
    const float* b2    = (const float*)d_in[5];
    const float* gamma = (const float*)d_in[6];
    float*       out   = (float*)d_out;

    k_deg_zero<<<(N_NODES + 255) / 256, 256>>>();
    k_sniff<<<1, 1>>>((const unsigned*)eiraw);
    k_cvt<<<(2 * N_EDGES + 255) / 256, 256>>>(eiraw);
    k_dinv<<<(N_NODES + 255) / 256, 256>>>();
    k_scan<<<1, 1024>>>();
    k_fill<<<(N_EDGES + 255) / 256, 256>>>();

    k_w1cvt<<<(F_IN * HID + 255) / 256, 256>>>(W1);
    k_w2cvt<<<(HID * N_CLS + 255) / 256, 256>>>(W2);
    cudaFuncSetAttribute(k_mlp, cudaFuncAttributeMaxDynamicSharedMemorySize, SMEM_T);
    k_mlp<<<(N_NODES + 127) / 128, 256, SMEM_T>>>(x, b1, b2, gamma);

    int cur = 0;
    for (int k = 1; k <= KSTEPS; k++) {
        k_spmv<<<(N_NODES + 7) / 8, 256>>>(cur, k, gamma);
        cur ^= 1;
    }

    k_lsm<<<(N_NODES + 7) / 8, 256>>>(out);
}

// round 7
// speedup vs baseline: 2.0506x; 1.1900x over previous
#include <cuda_runtime.h>
#include <cuda_bf16.h>
#include <cstdint>

#define N_NODES 100000
#define F_IN    512
#define HID     256
#define N_CLS   32
#define N_EDGES 3200000
#define KSTEPS  10
#define NBLK    ((N_NODES + 255) / 256)   // 391

// ---------------- device scratch ----------------
__device__ __align__(128) float g_h0[(size_t)N_NODES * N_CLS];   // p ping
__device__ __align__(128) float g_h1[(size_t)N_NODES * N_CLS];   // p pong
__device__ __align__(128) float g_acc[(size_t)N_NODES * N_CLS];
__device__ __align__(128) int   g_deg[N_NODES];
__device__ __align__(128) int   g_rowptr[N_NODES + 1];
__device__ __align__(128) int   g_pos[N_NODES];
__device__ __align__(128) int   g_srcv[N_EDGES];
__device__ __align__(128) int   g_dstv[N_EDGES];
__device__ __align__(128) int   g_csr_idx[N_EDGES];
__device__ __align__(128) int   g_bsum[512];
__device__ __align__(128) int   g_boff[512];
__device__ __align__(128) __nv_bfloat16 g_w1t_hi[(size_t)HID * F_IN];
__device__ __align__(128) __nv_bfloat16 g_w1t_lo[(size_t)HID * F_IN];
__device__ __align__(128) __nv_bfloat16 g_w2t_hi[(size_t)N_CLS * HID];
__device__ __align__(128) __nv_bfloat16 g_w2t_lo[(size_t)N_CLS * HID];
__device__ int g_is64;

// ---------------- edge index dtype sniff + convert (+deg count fused) ----------------
__global__ void k_sniff(const unsigned* __restrict__ raw) {
    unsigned orv = 0;
#pragma unroll
    for (int i = 0; i < 16; i++) orv |= raw[2 * i + 1];
    g_is64 = (orv == 0u) ? 1 : 0;
}

__global__ void k_cvt(const void* __restrict__ raw) {
    int i = blockIdx.x * blockDim.x + threadIdx.x;
    if (i >= 2 * N_EDGES) return;
    int v;
    if (g_is64) v = (int)((const long long*)raw)[i];
    else        v = ((const int*)raw)[i];
    if (i < N_EDGES) g_srcv[i] = v;
    else { g_dstv[i - N_EDGES] = v; atomicAdd(&g_deg[v], 1); }
}

__global__ void k_deg_zero() {
    int i = blockIdx.x * blockDim.x + threadIdx.x;
    if (i < N_NODES) g_deg[i] = 0;
}

// ---------------- parallel exclusive scan of g_deg -> g_rowptr/g_pos ----------------
__global__ __launch_bounds__(256) void k_scan1() {
    __shared__ int wsum[8];
    int tid = threadIdx.x;
    int i = blockIdx.x * 256 + tid;
    int v = (i < N_NODES) ? g_deg[i] : 0;
    int x = v;
#pragma unroll
    for (int o = 16; o; o >>= 1) x += __shfl_down_sync(0xffffffffu, x, o);
    if ((tid & 31) == 0) wsum[tid >> 5] = x;
    __syncthreads();
    if (tid < 8) {
        int y = wsum[tid];
#pragma unroll
        for (int o = 4; o; o >>= 1) y += __shfl_down_sync(0xffu, y, o);
        if (tid == 0) g_bsum[blockIdx.x] = y;
    }
}

__global__ __launch_bounds__(512) void k_scan2() {
    __shared__ int wsum[16];
    int tid = threadIdx.x;
    int lane = tid & 31, w = tid >> 5;
    int v = (tid < NBLK) ? g_bsum[tid] : 0;
    int x = v;
#pragma unroll
    for (int o = 1; o < 32; o <<= 1) {
        int t = __shfl_up_sync(0xffffffffu, x, o);
        if (lane >= o) x += t;
    }
    if (lane == 31) wsum[w] = x;
    __syncthreads();
    if (tid < 16) {
        int y = wsum[tid];
#pragma unroll
        for (int o = 1; o < 16; o <<= 1) {
            int t = __shfl_up_sync(0xffffu, y, o);
            if (tid >= o) y += t;
        }
        wsum[tid] = y;
    }
    __syncthreads();
    int pre = (w > 0) ? wsum[w - 1] : 0;
    int excl = pre + x - v;
    g_boff[tid] = excl;
    if (tid == NBLK) g_rowptr[N_NODES] = excl;
}

__global__ __launch_bounds__(256) void k_scan3() {
    __shared__ int wsum[8];
    int tid = threadIdx.x;
    int i = blockIdx.x * 256 + tid;
    int lane = tid & 31, w = tid >> 5;
    int v = (i < N_NODES) ? g_deg[i] : 0;
    int x = v;
#pragma unroll
    for (int o = 1; o < 32; o <<= 1) {
        int t = __shfl_up_sync(0xffffffffu, x, o);
        if (lane >= o) x += t;
    }
    if (lane == 31) wsum[w] = x;
    __syncthreads();
    if (tid < 8) {
        int y = wsum[tid];
#pragma unroll
        for (int o = 1; o < 8; o <<= 1) {
            int t = __shfl_up_sync(0xffu, y, o);
            if (tid >= o) y += t;
        }
        wsum[tid] = y;
    }
    __syncthreads();
    int pre = (w > 0) ? wsum[w - 1] : 0;
    int excl = g_boff[blockIdx.x] + pre + x - v;
    if (i < N_NODES) { g_rowptr[i] = excl; g_pos[i] = excl; }
}

__global__ void k_fill() {
    int e = blockIdx.x * blockDim.x + threadIdx.x;
    if (e >= N_EDGES) return;
    int s = g_srcv[e], d = g_dstv[e];
    int p = atomicAdd(&g_pos[d], 1);
    g_csr_idx[p] = s;
}

// ---------------- weight conversions ----------------
__global__ void k_w1cvt(const float* __restrict__ W1) {
    int i = blockIdx.x * blockDim.x + threadIdx.x;
    if (i >= F_IN * HID) return;
    int k = i / HID, n = i % HID;
    float v = W1[i];
    __nv_bfloat16 h = __float2bfloat16(v);
    g_w1t_hi[(size_t)n * F_IN + k] = h;
    g_w1t_lo[(size_t)n * F_IN + k] = __float2bfloat16(v - __bfloat162float(h));
}

__global__ void k_w2cvt(const float* __restrict__ W2) {
    int i = blockIdx.x * blockDim.x + threadIdx.x;
    if (i >= HID * N_CLS) return;
    int k = i / N_CLS, n = i % N_CLS;
    float v = W2[i];
    __nv_bfloat16 h = __float2bfloat16(v);
    g_w2t_hi[(size_t)n * HID + k] = h;
    g_w2t_lo[(size_t)n * HID + k] = __float2bfloat16(v - __bfloat162float(h));
}

// ---------------- fused MLP: h0 = relu(x@W1+b1)@W2 + b2 ----------------
// stores p0 = dinv*h0 into g_h0 and acc = gamma0*h0 into g_acc
#define ST1  72
#define ST2  264

#define ASH_O   0u
#define ASL_O   18432u
#define BSH_O   36864u
#define BSL_O   73728u
#define ZHI_O   0u
#define ZLO_O   67584u
#define W2HI_O  135168u
#define W2LO_O  152064u
#define B2_O    168960u
#define BIAS_O  169088u
#define SMEM_T  170112u

#define MMA16816(c, a, b) \
    asm volatile("mma.sync.aligned.m16n8k16.row.col.f32.bf16.bf16.f32 " \
                 "{%0,%1,%2,%3},{%4,%5,%6,%7},{%8,%9},{%0,%1,%2,%3};" \
                 : "+f"((c)[0]), "+f"((c)[1]), "+f"((c)[2]), "+f"((c)[3]) \
                 : "r"((a)[0]), "r"((a)[1]), "r"((a)[2]), "r"((a)[3]), \
                   "r"((b)[0]), "r"((b)[1]))

__device__ __forceinline__ uint32_t pack_hi(float a, float b) {
    __nv_bfloat16 h0 = __float2bfloat16(a), h1 = __float2bfloat16(b);
    return (uint32_t)__bfloat16_as_ushort(h0) | ((uint32_t)__bfloat16_as_ushort(h1) << 16);
}
__device__ __forceinline__ uint32_t pack_lo(float a, float b) {
    __nv_bfloat16 h0 = __float2bfloat16(a), h1 = __float2bfloat16(b);
    float r0 = a - __bfloat162float(h0), r1 = b - __bfloat162float(h1);
    __nv_bfloat16 l0 = __float2bfloat16(r0), l1 = __float2bfloat16(r1);
    return (uint32_t)__bfloat16_as_ushort(l0) | ((uint32_t)__bfloat16_as_ushort(l1) << 16);
}

__global__ __launch_bounds__(256, 1) void k_mlp(const float* __restrict__ x,
                                                const float* __restrict__ b1,
                                                const float* __restrict__ b2,
                                                const float* __restrict__ gamma) {
    extern __shared__ __align__(16) char sm[];
    __nv_bfloat16* as_hi = (__nv_bfloat16*)(sm + ASH_O);
    __nv_bfloat16* as_lo = (__nv_bfloat16*)(sm + ASL_O);
    __nv_bfloat16* bs_hi = (__nv_bfloat16*)(sm + BSH_O);
    __nv_bfloat16* bs_lo = (__nv_bfloat16*)(sm + BSL_O);
    uint32_t* zhi = (uint32_t*)(sm + ZHI_O);
    uint32_t* zlo = (uint32_t*)(sm + ZLO_O);
    __nv_bfloat16* w2hi = (__nv_bfloat16*)(sm + W2HI_O);
    __nv_bfloat16* w2lo = (__nv_bfloat16*)(sm + W2LO_O);
    float* b2s = (float*)(sm + B2_O);
    float* bias_s = (float*)(sm + BIAS_O);

    const int tid = threadIdx.x;
    const int wid = tid >> 5, lane = tid & 31;
    const int gq = lane >> 2, tg = lane & 3;
    const int rowBase = blockIdx.x * 128;
    const int wr = (wid >> 2) * 64, wc = (wid & 3) * 64;

    bias_s[tid] = b1[tid];
    if (tid < N_CLS) b2s[tid] = b2[tid];
    for (int i = tid; i < 1024; i += 256) {
        int n = i >> 5, k8 = (i & 31) * 8;
        *(uint4*)(w2hi + n * ST2 + k8) = *(const uint4*)(g_w2t_hi + n * HID + k8);
        *(uint4*)(w2lo + n * ST2 + k8) = *(const uint4*)(g_w2t_lo + n * HID + k8);
    }

    float acc[4][8][4];
#pragma unroll
    for (int a = 0; a < 4; a++)
#pragma unroll
        for (int b = 0; b < 8; b++)
#pragma unroll
            for (int c = 0; c < 4; c++) acc[a][b][c] = 0.f;

    for (int ch = 0; ch < 8; ch++) {
        const int k0 = ch * 64;
        __syncthreads();
        for (int i = tid; i < 2048; i += 256) {
            int r = i >> 4, cc = (i & 15) * 4;
            float4 v = make_float4(0.f, 0.f, 0.f, 0.f);
            int grow = rowBase + r;
            if (grow < N_NODES)
                v = *(const float4*)(x + (size_t)grow * F_IN + k0 + cc);
            uint2 ph = make_uint2(pack_hi(v.x, v.y), pack_hi(v.z, v.w));
            uint2 pl = make_uint2(pack_lo(v.x, v.y), pack_lo(v.z, v.w));
            *(uint2*)(as_hi + r * ST1 + cc) = ph;
            *(uint2*)(as_lo + r * ST1 + cc) = pl;
        }
        for (int i = tid; i < 2048; i += 256) {
            int n = i >> 3, k8 = (i & 7) * 8;
            size_t gi = (size_t)n * F_IN + k0 + k8;
            *(uint4*)(bs_hi + n * ST1 + k8) = *(const uint4*)(g_w1t_hi + gi);
            *(uint4*)(bs_lo + n * ST1 + k8) = *(const uint4*)(g_w1t_lo + gi);
        }
        __syncthreads();

#pragma unroll
        for (int ks = 0; ks < 4; ks++) {
            const int ko = ks * 16;
            uint32_t ah[4][4], al[4][4];
#pragma unroll
            for (int mt = 0; mt < 4; mt++) {
                int r0 = wr + mt * 16 + gq;
                ah[mt][0] = *(const uint32_t*)(as_hi + r0 * ST1 + ko + 2 * tg);
                ah[mt][1] = *(const uint32_t*)(as_hi + (r0 + 8) * ST1 + ko + 2 * tg);
                ah[mt][2] = *(const uint32_t*)(as_hi + r0 * ST1 + ko + 8 + 2 * tg);
                ah[mt][3] = *(const uint32_t*)(as_hi + (r0 + 8) * ST1 + ko + 8 + 2 * tg);
                al[mt][0] = *(const uint32_t*)(as_lo + r0 * ST1 + ko + 2 * tg);
                al[mt][1] = *(const uint32_t*)(as_lo + (r0 + 8) * ST1 + ko + 2 * tg);
                al[mt][2] = *(const uint32_t*)(as_lo + r0 * ST1 + ko + 8 + 2 * tg);
                al[mt][3] = *(const uint32_t*)(as_lo + (r0 + 8) * ST1 + ko + 8 + 2 * tg);
            }
#pragma unroll
            for (int nt = 0; nt < 8; nt++) {
                int n0 = wc + nt * 8 + gq;
                uint32_t bh[2], bl[2];
                bh[0] = *(const uint32_t*)(bs_hi + n0 * ST1 + ko + 2 * tg);
                bh[1] = *(const uint32_t*)(bs_hi + n0 * ST1 + ko + 8 + 2 * tg);
                bl[0] = *(const uint32_t*)(bs_lo + n0 * ST1 + ko + 2 * tg);
                bl[1] = *(const uint32_t*)(bs_lo + n0 * ST1 + ko + 8 + 2 * tg);
#pragma unroll
                for (int mt = 0; mt < 4; mt++) {
                    MMA16816(acc[mt][nt], ah[mt], bh);
                    MMA16816(acc[mt][nt], ah[mt], bl);
                    MMA16816(acc[mt][nt], al[mt], bh);
                }
            }
        }
    }

    __syncthreads();

    // phase1 epilogue: bias+relu -> z bf16 hi/lo in smem
#pragma unroll
    for (int mt = 0; mt < 4; mt++) {
        int r0 = wr + mt * 16 + gq;
        int r1 = r0 + 8;
#pragma unroll
        for (int nt = 0; nt < 8; nt++) {
            int cl = wc + nt * 8 + 2 * tg;
            float bx = bias_s[cl], by = bias_s[cl + 1];
            float o0 = fmaxf(acc[mt][nt][0] + bx, 0.f);
            float o1 = fmaxf(acc[mt][nt][1] + by, 0.f);
            float o2 = fmaxf(acc[mt][nt][2] + bx, 0.f);
            float o3 = fmaxf(acc[mt][nt][3] + by, 0.f);
            int w0 = r0 * 132 + (cl >> 1);
            int w1 = r1 * 132 + (cl >> 1);
            zhi[w0] = pack_hi(o0, o1); zlo[w0] = pack_lo(o0, o1);
            zhi[w1] = pack_hi(o2, o3); zlo[w1] = pack_lo(o2, o3);
        }
    }
    __syncthreads();

    // phase2: h0 = z @ W2 + b2 ; p0 = dinv*h0 ; acc = gamma0*h0
    float acc2[4][4];
#pragma unroll
    for (int a = 0; a < 4; a++)
#pragma unroll
        for (int c = 0; c < 4; c++) acc2[a][c] = 0.f;

    const int rl0 = wid * 16 + gq;
#pragma unroll
    for (int ks = 0; ks < 16; ks++) {
        const int kw = ks * 8 + tg;
        uint32_t ah[4], al[4];
        ah[0] = zhi[rl0 * 132 + kw];
        ah[1] = zhi[(rl0 + 8) * 132 + kw];
        ah[2] = zhi[rl0 * 132 + kw + 4];
        ah[3] = zhi[(rl0 + 8) * 132 + kw + 4];
        al[0] = zlo[rl0 * 132 + kw];
        al[1] = zlo[(rl0 + 8) * 132 + kw];
        al[2] = zlo[rl0 * 132 + kw + 4];
        al[3] = zlo[(rl0 + 8) * 132 + kw + 4];
#pragma unroll
        for (int nt = 0; nt < 4; nt++) {
            int n0 = nt * 8 + gq;
            uint32_t bh[2], bl[2];
            bh[0] = *(const uint32_t*)(w2hi + n0 * ST2 + ks * 16 + 2 * tg);
            bh[1] = *(const uint32_t*)(w2hi + n0 * ST2 + ks * 16 + 8 + 2 * tg);
            bl[0] = *(const uint32_t*)(w2lo + n0 * ST2 + ks * 16 + 2 * tg);
            bl[1] = *(const uint32_t*)(w2lo + n0 * ST2 + ks * 16 + 8 + 2 * tg);
            MMA16816(acc2[nt], ah, bh);
            MMA16816(acc2[nt], ah, bl);
            MMA16816(acc2[nt], al, bh);
        }
    }

    float g0 = gamma[0];
    int row0 = rowBase + rl0, row1 = row0 + 8;
    float di0 = 1.f, di1 = 1.f;
    if (row0 < N_NODES) di0 = rsqrtf(1.0f + (float)g_deg[row0]);
    if (row1 < N_NODES) di1 = rsqrtf(1.0f + (float)g_deg[row1]);
#pragma unroll
    for (int nt = 0; nt < 4; nt++) {
        int cl = nt * 8 + 2 * tg;
        float bx = b2s[cl], by = b2s[cl + 1];
        if (row0 < N_NODES) {
            float hx = acc2[nt][0] + bx, hy = acc2[nt][1] + by;
            *(float2*)(g_h0 + (size_t)row0 * N_CLS + cl) = make_float2(di0 * hx, di0 * hy);
            *(float2*)(g_acc + (size_t)row0 * N_CLS + cl) = make_float2(g0 * hx, g0 * hy);
        }
        if (row1 < N_NODES) {
            float hx = acc2[nt][2] + bx, hy = acc2[nt][3] + by;
            *(float2*)(g_h0 + (size_t)row1 * N_CLS + cl) = make_float2(di1 * hx, di1 * hy);
            *(float2*)(g_acc + (size_t)row1 * N_CLS + cl) = make_float2(g0 * hx, g0 * hy);
        }
    }
}

// ---------------- SpMV step on p = dinv*h ----------------
// p_new[d] = (sum_{src} p[src] + p[d]) / (1+deg[d])
// h_new[d] = sqrt(1+deg[d]) * p_new[d] ; acc += gamma[gi]*h_new
template <bool LAST>
__global__ __launch_bounds__(256) void k_spmv(int cur, int gi,
                                              const float* __restrict__ gamma,
                                              float* __restrict__ out) {
    __shared__ int est[8][32];
    const float* pc = cur ? g_h1 : g_h0;
    float* pn = cur ? g_h0 : g_h1;

    const int ws = threadIdx.x >> 5;
    int n = (blockIdx.x * blockDim.x + threadIdx.x) >> 5;
    int lane = threadIdx.x & 31;
    if (n >= N_NODES) return;
    int beg = g_rowptr[n], end = g_rowptr[n + 1];
    float acc = pc[(size_t)n * N_CLS + lane];   // self loop

    for (int e0 = beg; e0 < end; e0 += 32) {
        int ee = e0 + lane;
        if (ee < end) est[ws][lane] = g_csr_idx[ee];
        __syncwarp();
        int cnt = end - e0; if (cnt > 32) cnt = 32;
        int i = 0;
        for (; i + 4 <= cnt; i += 4) {
            int s0 = est[ws][i], s1 = est[ws][i + 1];
            int s2 = est[ws][i + 2], s3 = est[ws][i + 3];
            float v0 = pc[(size_t)s0 * N_CLS + lane];
            float v1 = pc[(size_t)s1 * N_CLS + lane];
            float v2 = pc[(size_t)s2 * N_CLS + lane];
            float v3 = pc[(size_t)s3 * N_CLS + lane];
            acc += v0; acc += v1; acc += v2; acc += v3;
        }
        for (; i < cnt; i++)
            acc += pc[(size_t)est[ws][i] * N_CLS + lane];
        __syncwarp();
    }

    float fdeg1 = 1.0f + (float)(end - beg);
    float p_new = acc * (1.0f / fdeg1);
    float h_new = p_new * sqrtf(fdeg1);
    float gk = gamma[gi];
    size_t o = (size_t)n * N_CLS + lane;

    if (!LAST) {
        pn[o] = p_new;
        g_acc[o] += gk * h_new;
    } else {
        float v = g_acc[o] + gk * h_new;
        float m = v;
#pragma unroll
        for (int off = 16; off; off >>= 1)
            m = fmaxf(m, __shfl_xor_sync(0xffffffffu, m, off));
        float e = expf(v - m);
        float sum = e;
#pragma unroll
        for (int off = 16; off; off >>= 1)
            sum += __shfl_xor_sync(0xffffffffu, sum, off);
        out[o] = v - m - logf(sum);
    }
}

// ---------------- launch ----------------
extern "C" void kernel_launch(void* const* d_in, const int* in_sizes, int n_in,
                              void* d_out, int out_size) {
    const float* x     = (const float*)d_in[0];
    const void*  eiraw = d_in[1];
    const float* W1    = (const float*)d_in[2];
    const float* b1    = (const float*)d_in[3];
    const float* W2    = (const float*)d_in[4];
    const float* b2    = (const float*)d_in[5];
    const float* gamma = (const float*)d_in[6];
    float*       out   = (float*)d_out;

    k_deg_zero<<<NBLK, 256>>>();
    k_sniff<<<1, 1>>>((const unsigned*)eiraw);
    k_cvt<<<(2 * N_EDGES + 255) / 256, 256>>>(eiraw);
    k_scan1<<<NBLK, 256>>>();
    k_scan2<<<1, 512>>>();
    k_scan3<<<NBLK, 256>>>();
    k_fill<<<(N_EDGES + 255) / 256, 256>>>();

    k_w1cvt<<<(F_IN * HID + 255) / 256, 256>>>(W1);
    k_w2cvt<<<(HID * N_CLS + 255) / 256, 256>>>(W2);
    cudaFuncSetAttribute(k_mlp, cudaFuncAttributeMaxDynamicSharedMemorySize, SMEM_T);
    k_mlp<<<(N_NODES + 127) / 128, 256, SMEM_T>>>(x, b1, b2, gamma);

    int cur = 0;
    const int spmvBlocks = (N_NODES + 7) / 8;
    for (int k = 1; k < KSTEPS; k++) {
        k_spmv<false><<<spmvBlocks, 256>>>(cur, k, gamma, out);
        cur ^= 1;
    }
    k_spmv<true><<<spmvBlocks, 256>>>(cur, KSTEPS, gamma, out);
}